// round 2
// baseline (speedup 1.0000x reference)
#include <cuda_runtime.h>
#include <cmath>

namespace {
constexpr int D = 192;
constexpr int H = 48;
constexpr int W = 48;
constexpr int PLANE = H * W;          // 2304
constexpr int VOX = D * PLANE;        // 442368
constexpr int MH = 384;               // hyper channels
constexpr int NCH = 24;               // conv3d out channels

constexpr int HALF_H = 24;            // output rows per CTA
constexpr int NT = 288;               // threads: 24 rows * 12 groups of 4 px

// x window in smem: input rows h0-5 .. h0+28 (34 rows), cols padded +-5, pitch 60
constexpr int XROWS = 34;
constexpr int XPITCH = 60;
constexpr int XSLICE = XROWS * XPITCH;     // 2040
constexpr int SX_SZ = 6 * XSLICE;          // 12240 (6 depth slices: d-5..d)
constexpr int W1_SZ = NCH * 6 * 11 * 12;   // 19008 (kd 0..5, kh 0..10, kw padded to 12)
constexpr int HYPROWS = 26;                // input rows h0-1 .. h0+24
constexpr int HYPPITCH = 52;
constexpr int HYP_SZ = HYPROWS * HYPPITCH; // 1352
constexpr int HC_SZ = HALF_H * W;          // 1152
constexpr int W3_SZ = MH * 9;              // 3456
constexpr int WA_SZ = 48 * 28;             // 1344 (rows padded 25->28)
constexpr int WB_SZ = 96 * 48;             // 4608
constexpr int WCT_SZ = 96 * 12;            // 1152 (Wc transposed, pitch 12)

constexpr int OFF_X   = 0;
constexpr int OFF_W1  = OFF_X + SX_SZ;
constexpr int OFF_HYP = OFF_W1 + W1_SZ;
constexpr int OFF_HC  = OFF_HYP + HYP_SZ;
constexpr int OFF_W3  = OFF_HC + HC_SZ;
constexpr int OFF_WA  = OFF_W3 + W3_SZ;
constexpr int OFF_WB  = OFF_WA + WA_SZ;
constexpr int OFF_WCT = OFF_WB + WB_SZ;
constexpr int OFF_BA  = OFF_WCT + WCT_SZ;
constexpr int OFF_BB  = OFF_BA + 48;
constexpr int OFF_BC  = OFF_BB + 96;
constexpr int OFF_B1  = OFF_BC + 12;
constexpr int SMEM_FLOATS = OFF_B1 + 24;   // 44492
constexpr int SMEM_BYTES = SMEM_FLOATS * 4; // 177968
}

// Scratch for conv3d output x1[24 ch] per depth slice. Each CTA writes only
// its own (d, half-plane) region and reads it back within the same CTA after
// a __syncthreads() — no inter-CTA communication. Static __device__ array is
// the sanctioned no-allocation scratch mechanism.
__device__ float g_x1[(size_t)NCH * D * PLANE];

__global__ __launch_bounds__(NT, 1)
void wg_fused_kernel(const float* __restrict__ x, const float* __restrict__ hyper,
                     const float* __restrict__ W3, const float* __restrict__ b3,
                     const float* __restrict__ W1, const float* __restrict__ b1,
                     const float* __restrict__ Wa, const float* __restrict__ ba,
                     const float* __restrict__ Wb, const float* __restrict__ bb,
                     const float* __restrict__ Wc, const float* __restrict__ bc,
                     float* __restrict__ out)
{
    extern __shared__ float sm[];
    float* s_x   = sm + OFF_X;
    float* s_w1  = sm + OFF_W1;
    float* s_hyp = sm + OFF_HYP;
    float* s_hc  = sm + OFF_HC;
    float* s_w3  = sm + OFF_W3;
    float* s_wa  = sm + OFF_WA;
    float* s_wb  = sm + OFF_WB;
    float* s_wct = sm + OFF_WCT;
    float* s_ba  = sm + OFF_BA;
    float* s_bb  = sm + OFF_BB;
    float* s_bc  = sm + OFF_BC;
    float* s_b1  = sm + OFF_B1;

    const int tid = threadIdx.x;
    const int d   = blockIdx.x >> 1;
    const int h0  = (blockIdx.x & 1) * HALF_H;
    const int rowg = tid / 12;       // 0..23 local output row
    const int wg   = tid % 12;       // 0..11 group of 4 pixels
    const int x0   = wg * 4;

    // ---------------- Phase A: zero halos, stage weights ----------------
    for (int i = tid; i < SX_SZ; i += NT) s_x[i] = 0.f;
    for (int i = tid; i < HYP_SZ; i += NT) s_hyp[i] = 0.f;
    for (int i = tid; i < W3_SZ; i += NT) s_w3[i] = W3[d * W3_SZ + i];
    for (int i = tid; i < WA_SZ; i += NT) {
        int r = i / 28, c = i % 28;
        s_wa[i] = (c < 25) ? Wa[r * 25 + c] : 0.f;
    }
    for (int i = tid; i < WB_SZ; i += NT) s_wb[i] = Wb[i];
    for (int i = tid; i < WCT_SZ; i += NT) {
        int j = i / 12, o = i % 12;
        s_wct[i] = (o < 9) ? Wc[o * 96 + j] : 0.f;
    }
    for (int i = tid; i < 48; i += NT) s_ba[i] = ba[i];
    for (int i = tid; i < 96; i += NT) s_bb[i] = bb[i];
    for (int i = tid; i < 12; i += NT) s_bc[i] = (i < 9) ? bc[i] : 0.f;
    for (int i = tid; i < 24; i += NT) s_b1[i] = b1[i];
    // masked conv3d weights, mask A: flat index (kd*121+kh*11+kw) < 665
    for (int i = tid; i < W1_SZ; i += NT) {
        int c = i / 792, rem = i % 792;
        int kd = rem / 132, r2 = rem % 132;
        int kh = r2 / 12, kw = r2 % 12;
        float v = 0.f;
        if (kw < 11) {
            int flat = kd * 121 + kh * 11 + kw;
            if (flat < 665) v = W1[c * 1331 + flat];
        }
        s_w1[i] = v;
    }
    __syncthreads();

    // ---------------- Phase B: fill x slices (depths d-5..d) ----------------
    for (int s = 0; s < 6; s++) {
        int sd = d - 5 + s;
        if (sd < 0) continue;
        const float* xp = x + (size_t)sd * PLANE;
        for (int i = tid; i < XROWS * (W / 4); i += NT) {
            int r = i / 12, x4 = (i % 12) * 4;
            int iy = h0 - 5 + r;
            if (iy >= 0 && iy < H) {
                float4 v = *(const float4*)(xp + iy * W + x4);
                float* drow = s_x + s * XSLICE + r * XPITCH + 5 + x4;
                drow[0] = v.x; drow[1] = v.y; drow[2] = v.z; drow[3] = v.w;
            }
        }
    }

    // ---------------- Phase C: conv2d for output channel d ----------------
    float c2d0 = b3[d], c2d1 = c2d0, c2d2 = c2d0, c2d3 = c2d0;
    #pragma unroll 1
    for (int ic = 0; ic < MH; ic++) {
        const float* hp = hyper + (size_t)ic * PLANE;
        for (int i = tid; i < HYPROWS * (W / 4); i += NT) {   // 312
            int r = i / 12, x4 = (i % 12) * 4;
            int iy = h0 - 1 + r;
            float4 v = make_float4(0.f, 0.f, 0.f, 0.f);
            if (iy >= 0 && iy < H) v = *(const float4*)(hp + iy * W + x4);
            float* drow = s_hyp + r * HYPPITCH + 1 + x4;
            drow[0] = v.x; drow[1] = v.y; drow[2] = v.z; drow[3] = v.w;
        }
        __syncthreads();
        const float* wt = s_w3 + ic * 9;
        #pragma unroll
        for (int rt = 0; rt < 3; rt++) {
            const float4* hr = (const float4*)(s_hyp + (rowg + rt) * HYPPITCH + x0);
            float4 p = hr[0], q = hr[1];
            float wn0 = p.x, wn1 = p.y, wn2 = p.z, wn3 = p.w, wn4 = q.x, wn5 = q.y;
            float u0 = wt[rt * 3 + 0], u1 = wt[rt * 3 + 1], u2 = wt[rt * 3 + 2];
            c2d0 = fmaf(u0, wn0, c2d0); c2d0 = fmaf(u1, wn1, c2d0); c2d0 = fmaf(u2, wn2, c2d0);
            c2d1 = fmaf(u0, wn1, c2d1); c2d1 = fmaf(u1, wn2, c2d1); c2d1 = fmaf(u2, wn3, c2d1);
            c2d2 = fmaf(u0, wn2, c2d2); c2d2 = fmaf(u1, wn3, c2d2); c2d2 = fmaf(u2, wn4, c2d2);
            c2d3 = fmaf(u0, wn3, c2d3); c2d3 = fmaf(u1, wn4, c2d3); c2d3 = fmaf(u2, wn5, c2d3);
        }
        __syncthreads();
    }
    s_hc[rowg * W + x0 + 0] = c2d0;
    s_hc[rowg * W + x0 + 1] = c2d1;
    s_hc[rowg * W + x0 + 2] = c2d2;
    s_hc[rowg * W + x0 + 3] = c2d3;

    // ---------------- Phase D: masked conv3d (causal in depth) ----------------
    #pragma unroll 1
    for (int c = 0; c < NCH; c++) {
        float a0 = s_b1[c], a1 = a0, a2 = a0, a3 = a0;
        const float* wcb = s_w1 + c * 792;
        #pragma unroll 1
        for (int kd = 0; kd < 6; kd++) {
            const float* xs = s_x + kd * XSLICE + rowg * XPITCH + x0;
            const float* ws = wcb + kd * 132;
            const int khmax = (kd < 5) ? 11 : 6;   // mask: kd=5 only kh<=5 nonzero
            #pragma unroll 1
            for (int kh = 0; kh < khmax; kh++) {
                const float4* xr = (const float4*)(xs + kh * XPITCH);
                float4 v0 = xr[0], v1 = xr[1], v2 = xr[2], v3 = xr[3];
                const float4* wr = (const float4*)(ws + kh * 12);
                float4 u0 = wr[0], u1 = wr[1], u2 = wr[2];
                float wn[16] = {v0.x, v0.y, v0.z, v0.w, v1.x, v1.y, v1.z, v1.w,
                                v2.x, v2.y, v2.z, v2.w, v3.x, v3.y, v3.z, v3.w};
                float wv[11] = {u0.x, u0.y, u0.z, u0.w, u1.x, u1.y, u1.z, u1.w,
                                u2.x, u2.y, u2.z};
                #pragma unroll
                for (int kw = 0; kw < 11; kw++) {
                    a0 = fmaf(wv[kw], wn[kw + 0], a0);
                    a1 = fmaf(wv[kw], wn[kw + 1], a1);
                    a2 = fmaf(wv[kw], wn[kw + 2], a2);
                    a3 = fmaf(wv[kw], wn[kw + 3], a3);
                }
            }
        }
        float4* dst = (float4*)(g_x1 + ((size_t)(d * NCH + c)) * PLANE
                                + (size_t)(h0 + rowg) * W + x0);
        *dst = make_float4(a0, a1, a2, a3);
    }
    __syncthreads();   // g_x1 + s_hc visible CTA-wide

    // ---------------- Phase E: per-voxel MLP + mixture CDF ----------------
    #pragma unroll 1
    for (int it = 0; it < 4; it++) {
        int lp = tid + it * NT;              // 0..1151
        int py = lp / W, px = lp % W;
        int gp = (h0 + py) * W + px;

        float t0[25];
        const float* xb = g_x1 + (size_t)d * NCH * PLANE + gp;
        #pragma unroll
        for (int c = 0; c < 24; c++) t0[c] = xb[(size_t)c * PLANE];
        t0[24] = s_hc[lp];

        float av[48];
        #pragma unroll
        for (int i = 0; i < 48; i++) {
            const float* wr = s_wa + i * 28;
            float s = s_ba[i];
            #pragma unroll
            for (int c = 0; c < 25; c++) s = fmaf(wr[c], t0[c], s);
            av[i] = fmaxf(s, 0.f);
        }

        float o9[9];
        #pragma unroll
        for (int o = 0; o < 9; o++) o9[o] = s_bc[o];
        #pragma unroll 2
        for (int j = 0; j < 96; j++) {
            const float4* wr = (const float4*)(s_wb + j * 48);
            float s = s_bb[j];
            #pragma unroll
            for (int q = 0; q < 12; q++) {
                float4 w4 = wr[q];
                s = fmaf(w4.x, av[4 * q + 0], s);
                s = fmaf(w4.y, av[4 * q + 1], s);
                s = fmaf(w4.z, av[4 * q + 2], s);
                s = fmaf(w4.w, av[4 * q + 3], s);
            }
            s = fmaxf(s, 0.f);
            const float4* cr = (const float4*)(s_wct + j * 12);
            float4 q0 = cr[0], q1 = cr[1], q2 = cr[2];
            o9[0] = fmaf(q0.x, s, o9[0]);
            o9[1] = fmaf(q0.y, s, o9[1]);
            o9[2] = fmaf(q0.z, s, o9[2]);
            o9[3] = fmaf(q0.w, s, o9[3]);
            o9[4] = fmaf(q1.x, s, o9[4]);
            o9[5] = fmaf(q1.y, s, o9[5]);
            o9[6] = fmaf(q1.z, s, o9[6]);
            o9[7] = fmaf(q1.w, s, o9[7]);
            o9[8] = fmaf(q2.x, s, o9[8]);
        }

        float xv = s_x[5 * XSLICE + (py + 5) * XPITCH + px + 5];  // x[d, h0+py, px]

        float mx = fmaxf(o9[6], fmaxf(o9[7], o9[8]));
        float e0 = expf(o9[6] - mx), e1 = expf(o9[7] - mx), e2 = expf(o9[8] - mx);
        float inv = 1.f / (e0 + e1 + e2);
        float wsm[3] = {e0 * inv, e1 * inv, e2 * inv};

        float p3 = 0.f;
        #pragma unroll
        for (int k = 0; k < 3; k++) {
            float mu = o9[k];
            float scv = o9[3 + k];
            if (scv == 0.f) scv = 1e-9f;
            scv = fabsf(scv);
            float invs = 1.f / scv;
            float l = fabsf(normcdff((xv + 0.5f - mu) * invs)
                          - normcdff((xv - 0.5f - mu) * invs));
            p3 = fmaf(wsm[k], l, p3);
        }

        size_t ogp = (size_t)d * PLANE + gp;
        out[ogp] = p3;                                  // p3 first
        #pragma unroll
        for (int o = 0; o < 9; o++)
            out[(size_t)VOX + (size_t)o * VOX + ogp] = o9[o];   // then out[9,192,48,48]
    }
}

extern "C" void kernel_launch(void* const* d_in, const int* in_sizes, int n_in,
                              void* d_out, int out_size) {
    const float* x     = (const float*)d_in[0];
    const float* hyper = (const float*)d_in[1];
    const float* W3    = (const float*)d_in[2];
    const float* b3    = (const float*)d_in[3];
    const float* W1    = (const float*)d_in[4];
    const float* b1    = (const float*)d_in[5];
    const float* Wa    = (const float*)d_in[6];
    const float* ba    = (const float*)d_in[7];
    const float* Wb    = (const float*)d_in[8];
    const float* bb    = (const float*)d_in[9];
    const float* Wc    = (const float*)d_in[10];
    const float* bc    = (const float*)d_in[11];
    float* out = (float*)d_out;

    cudaFuncSetAttribute(wg_fused_kernel,
                         cudaFuncAttributeMaxDynamicSharedMemorySize, SMEM_BYTES);
    wg_fused_kernel<<<dim3(D * 2), NT, SMEM_BYTES>>>(
        x, hyper, W3, b3, W1, b1, Wa, ba, Wb, bb, Wc, bc, out);
}

// round 3
// speedup vs baseline: 3.1084x; 3.1084x over previous
#include <cuda_runtime.h>
#include <cmath>

namespace {
constexpr int D = 192, H = 48, W = 48, PLANE = 2304, VOX = 442368;

// ---- pack buffer layout (float offsets) ----
constexpr int PK_W1 = 0,            SZ_W1 = 19008;   // [cp12][kd6][kh11][kw12][2]
constexpr int PK_W3 = PK_W1 + SZ_W1, SZ_W3 = 663552; // [ic384][t9][dp96][2]
constexpr int PK_WA = PK_W3 + SZ_W3, SZ_WA = 1200;   // [c25][up24][2]
constexpr int PK_BA = PK_WA + SZ_WA, SZ_BA = 48;     // [up24][2]
constexpr int PK_WB = PK_BA + SZ_BA, SZ_WB = 4608;   // [h2][j48][up24][2]
constexpr int PK_BB = PK_WB + SZ_WB, SZ_BB = 96;     // [h2][up24][2]
constexpr int PK_WC = PK_BB + SZ_BB, SZ_WC = 1152;   // [j96][p6][2]
constexpr int PK_BC = PK_WC + SZ_WC, SZ_BC = 12;     // [p6][2]
constexpr int PK_TOTAL = PK_BC + SZ_BC;              // 689676

// K3 smem layout = contiguous copy of [PK_WA .. PK_BC+SZ_BC)
constexpr int SA_WA = 0, SA_BA = 1200, SA_WB = 1248, SA_BB = 5856,
              SA_WC = 5952, SA_BC = 7104, K3_SM = 7116;

// K2 smem
constexpr int K2_SX = 6 * 22 * 60;    // 7920 floats
constexpr int K2_SW = SZ_W1;          // 19008 floats
constexpr int K2_SMEM = (K2_SX + K2_SW) * 4;  // 107712 B
}

__device__ __align__(16) float g_pack[689680];
__device__ float g_h[VOX];
__device__ float g_x1[(size_t)24 * VOX];

// ---- f32x2 helpers ----
__device__ __forceinline__ unsigned long long splat2(float v) {
    unsigned long long r; asm("mov.b64 %0, {%1, %1};" : "=l"(r) : "f"(v)); return r;
}
__device__ __forceinline__ unsigned long long pack2(float a, float b) {
    unsigned long long r; asm("mov.b64 %0, {%1, %2};" : "=l"(r) : "f"(a), "f"(b)); return r;
}
__device__ __forceinline__ float2 unpack2(unsigned long long v) {
    float2 f; asm("mov.b64 {%0, %1}, %2;" : "=f"(f.x), "=f"(f.y) : "l"(v)); return f;
}
__device__ __forceinline__ void fma2(unsigned long long& a, unsigned long long w,
                                     unsigned long long x) {
    asm("fma.rn.f32x2 %0, %1, %2, %0;" : "+l"(a) : "l"(w), "l"(x));
}

// =============== K0: pack weights into pair layouts ===============
__global__ void pack_kernel(const float* __restrict__ W3, const float* __restrict__ W1,
                            const float* __restrict__ Wa, const float* __restrict__ ba,
                            const float* __restrict__ Wb, const float* __restrict__ bb,
                            const float* __restrict__ Wc, const float* __restrict__ bc) {
    int nt = gridDim.x * blockDim.x, tid = blockIdx.x * blockDim.x + threadIdx.x;
    // W1: masked (flat<665), channel pairs
    for (int i = tid; i < SZ_W1; i += nt) {
        int par = i & 1, q = i >> 1;
        int kw = q % 12; q /= 12;
        int kh = q % 11; q /= 11;
        int kd = q % 6;  int cp = q / 6;
        int c = cp * 2 + par;
        int flat = kd * 121 + kh * 11 + kw;
        float v = 0.f;
        if (kw < 11 && flat < 665) v = W1[c * 1331 + flat];
        g_pack[PK_W1 + i] = v;
    }
    // W3: d-pairs
    for (int i = tid; i < SZ_W3; i += nt) {
        int par = i & 1, q = i >> 1;
        int dp = q % 96; q /= 96;
        int t = q % 9;   int ic = q / 9;
        g_pack[PK_W3 + i] = W3[((size_t)(dp * 2 + par) * 384 + ic) * 9 + t];
    }
    // Wa / ba: unit pairs
    for (int i = tid; i < SZ_WA; i += nt) {
        int par = i & 1, q = i >> 1;
        int up = q % 24, c = q / 24;
        g_pack[PK_WA + i] = Wa[(up * 2 + par) * 25 + c];
    }
    for (int i = tid; i < SZ_BA; i += nt) {
        int par = i & 1, up = i >> 1;
        g_pack[PK_BA + i] = ba[up * 2 + par];
    }
    // Wb / bb
    for (int i = tid; i < SZ_WB; i += nt) {
        int par = i & 1, q = i >> 1;
        int up = q % 24; q /= 24;
        int j = q % 48;  int h = q / 48;
        g_pack[PK_WB + i] = Wb[(h * 48 + up * 2 + par) * 48 + j];
    }
    for (int i = tid; i < SZ_BB; i += nt) {
        int par = i & 1, q = i >> 1;
        int up = q % 24, h = q / 24;
        g_pack[PK_BB + i] = bb[h * 48 + up * 2 + par];
    }
    // Wc / bc (out pairs, pad o>=9)
    for (int i = tid; i < SZ_WC; i += nt) {
        int par = i & 1, q = i >> 1;
        int p = q % 6, j = q / 6;
        int o = p * 2 + par;
        g_pack[PK_WC + i] = (o < 9) ? Wc[o * 96 + j] : 0.f;
    }
    for (int i = tid; i < SZ_BC; i += nt) {
        int par = i & 1, p = i >> 1;
        int o = p * 2 + par;
        g_pack[PK_BC + i] = (o < 9) ? bc[o] : 0.f;
    }
}

// =============== K1: conv2d (hyper -> g_h), d-pairs packed ===============
__global__ __launch_bounds__(192, 2)
void conv2d_kernel(const float* __restrict__ hyper, const float* __restrict__ b3) {
    __shared__ float s_hyp[16 * 520];  // 16 ic x 10 rows x pitch 52
    int bx = blockIdx.x;
    int dg = bx % 48, rt = bx / 48;
    int r0 = rt * 8;
    int tid = threadIdx.x;
    int dhalf = tid / 96, r8 = (tid % 96) / 12, grp = tid % 12, x0 = grp * 4;
    int dp = dg * 2 + dhalf, d0 = dp * 2;

    unsigned long long acc[4];
    {
        unsigned long long bv = pack2(b3[d0], b3[d0 + 1]);
        acc[0] = bv; acc[1] = bv; acc[2] = bv; acc[3] = bv;
    }
    const unsigned long long* w3u = (const unsigned long long*)g_pack + (PK_W3 / 2);

    for (int icb = 0; icb < 384; icb += 16) {
        for (int i = tid; i < 16 * 520; i += 192) {
            int icl = i / 520, rr = (i % 520) / 52, cc = i % 52;
            int grow = r0 - 1 + rr, gcol = cc - 1;
            float v = 0.f;
            if (grow >= 0 && grow < 48 && gcol >= 0 && gcol < 48)
                v = hyper[(size_t)(icb + icl) * PLANE + grow * 48 + gcol];
            s_hyp[i] = v;
        }
        __syncthreads();
        #pragma unroll 2
        for (int icl = 0; icl < 16; icl++) {
            const float* hw = s_hyp + icl * 520 + r8 * 52 + x0;
            unsigned long long ss[3][6];
            #pragma unroll
            for (int ky = 0; ky < 3; ky++) {
                const float* row = hw + ky * 52;
                float4 a = *(const float4*)row;
                float2 b = *(const float2*)(row + 4);
                ss[ky][0] = splat2(a.x); ss[ky][1] = splat2(a.y); ss[ky][2] = splat2(a.z);
                ss[ky][3] = splat2(a.w); ss[ky][4] = splat2(b.x); ss[ky][5] = splat2(b.y);
            }
            const unsigned long long* wrow = w3u + (size_t)(icb + icl) * 9 * 96 + dp;
            #pragma unroll
            for (int ky = 0; ky < 3; ky++)
                #pragma unroll
                for (int kx = 0; kx < 3; kx++) {
                    unsigned long long wv = wrow[(ky * 3 + kx) * 96];
                    fma2(acc[0], wv, ss[ky][kx + 0]);
                    fma2(acc[1], wv, ss[ky][kx + 1]);
                    fma2(acc[2], wv, ss[ky][kx + 2]);
                    fma2(acc[3], wv, ss[ky][kx + 3]);
                }
        }
        __syncthreads();
    }
    float2 v0 = unpack2(acc[0]), v1 = unpack2(acc[1]);
    float2 v2 = unpack2(acc[2]), v3 = unpack2(acc[3]);
    int gp = (r0 + r8) * 48 + x0;
    *(float4*)(g_h + (size_t)d0 * PLANE + gp)       = make_float4(v0.x, v1.x, v2.x, v3.x);
    *(float4*)(g_h + (size_t)(d0 + 1) * PLANE + gp) = make_float4(v0.y, v1.y, v2.y, v3.y);
}

// =============== K2: masked conv3d (x -> g_x1), channel-pairs packed ===============
__global__ __launch_bounds__(576, 1)
void conv3d_kernel(const float* __restrict__ x, const float* __restrict__ b1) {
    extern __shared__ float sm[];
    float* s_x = sm;
    float* s_w = sm + K2_SX;

    int d = blockIdx.x >> 2, q = blockIdx.x & 3;
    int r0 = q * 12;
    int tid = threadIdx.x;
    int chalf = tid / 288, r12 = (tid % 288) / 24, grp = tid % 24, x0 = grp * 2;

    for (int i = tid; i < K2_SX; i += 576) s_x[i] = 0.f;
    for (int i = tid; i < K2_SW / 4; i += 576)
        ((float4*)s_w)[i] = ((const float4*)(g_pack + PK_W1))[i];
    __syncthreads();
    for (int i = tid; i < 6 * 22 * 12; i += 576) {
        int s = i / 264, rr = (i % 264) / 12, f4 = i % 12;
        int sd = d - 5 + s, grow = r0 - 5 + rr;
        if (sd >= 0 && grow >= 0 && grow < 48) {
            float4 v = *(const float4*)(x + (size_t)sd * PLANE + grow * 48 + f4 * 4);
            float* dst = s_x + (s * 22 + rr) * 60 + 5 + f4 * 4;
            dst[0] = v.x; dst[1] = v.y; dst[2] = v.z; dst[3] = v.w;
        }
    }
    __syncthreads();

    unsigned long long acc[6][2];
    #pragma unroll
    for (int c = 0; c < 6; c++) {
        int cp = chalf * 6 + c;
        unsigned long long bv = pack2(b1[cp * 2], b1[cp * 2 + 1]);
        acc[c][0] = bv; acc[c][1] = bv;
    }

    const ulonglong2* wb = (const ulonglong2*)s_w;
    int kd0 = (d >= 5) ? 0 : (5 - d);
    for (int kd = kd0; kd < 6; kd++) {
        int khmax = (kd < 5) ? 11 : 6;
        for (int kh = 0; kh < khmax; kh++) {
            const float* xr = s_x + (kd * 22 + (r12 + kh)) * 60 + x0;
            unsigned long long xs[12];
            #pragma unroll
            for (int i = 0; i < 12; i += 2) {
                float2 v = *(const float2*)(xr + i);
                xs[i] = splat2(v.x); xs[i + 1] = splat2(v.y);
            }
            #pragma unroll
            for (int c = 0; c < 6; c++) {
                int cp = chalf * 6 + c;
                const ulonglong2* wr = wb + ((cp * 6 + kd) * 11 + kh) * 6;
                ulonglong2 wA = wr[0], wB = wr[1], wC = wr[2],
                           wD = wr[3], wE = wr[4], wF = wr[5];
                unsigned long long wv[11] = {wA.x, wA.y, wB.x, wB.y, wC.x, wC.y,
                                             wD.x, wD.y, wE.x, wE.y, wF.x};
                #pragma unroll
                for (int kw = 0; kw < 11; kw++) {
                    fma2(acc[c][0], wv[kw], xs[kw]);
                    fma2(acc[c][1], wv[kw], xs[kw + 1]);
                }
            }
        }
    }

    int gp = (r0 + r12) * 48 + x0;
    #pragma unroll
    for (int c = 0; c < 6; c++) {
        int c0 = (chalf * 6 + c) * 2;
        float2 p0 = unpack2(acc[c][0]), p1 = unpack2(acc[c][1]);
        *(float2*)(g_x1 + ((size_t)d * 24 + c0) * PLANE + gp)     = make_float2(p0.x, p1.x);
        *(float2*)(g_x1 + ((size_t)d * 24 + c0 + 1) * PLANE + gp) = make_float2(p0.y, p1.y);
    }
}

// =============== K3: per-voxel MLP + mixture CDF ===============
__global__ __launch_bounds__(256, 2)
void mlp_kernel(const float* __restrict__ x, float* __restrict__ out) {
    __shared__ float sm[K3_SM + 4];
    int tid = threadIdx.x;
    for (int i = tid; i < K3_SM / 4; i += 256)
        ((float4*)sm)[i] = ((const float4*)(g_pack + PK_WA))[i];
    __syncthreads();
    const unsigned long long* su = (const unsigned long long*)sm;
    const ulonglong2* su2 = (const ulonglong2*)sm;

    int gp = blockIdx.x * 256 + tid;
    int d = gp / PLANE, p = gp % PLANE;

    float t[25];
    const float* xb = g_x1 + (size_t)d * 24 * PLANE + p;
    #pragma unroll
    for (int c = 0; c < 24; c++) t[c] = xb[(size_t)c * PLANE];
    t[24] = g_h[gp];

    // layer A: 25 -> 48 (24 pairs)
    unsigned long long accA[24];
    #pragma unroll
    for (int u = 0; u < 24; u++) accA[u] = su[SA_BA / 2 + u];
    #pragma unroll 5
    for (int c = 0; c < 25; c++) {
        unsigned long long ts = splat2(t[c]);
        const ulonglong2* wr = su2 + SA_WA / 4 + c * 12;
        #pragma unroll
        for (int u2 = 0; u2 < 12; u2++) {
            ulonglong2 ww = wr[u2];
            fma2(accA[2 * u2], ww.x, ts);
            fma2(accA[2 * u2 + 1], ww.y, ts);
        }
    }
    float a[48];
    #pragma unroll
    for (int u = 0; u < 24; u++) {
        float2 v = unpack2(accA[u]);
        a[2 * u] = fmaxf(v.x, 0.f);
        a[2 * u + 1] = fmaxf(v.y, 0.f);
    }

    unsigned long long oacc[5];
    #pragma unroll
    for (int pp = 0; pp < 5; pp++) oacc[pp] = su[SA_BC / 2 + pp];

    // layer B (48 -> 96 in two halves of 48) fused with layer C accumulation
    #pragma unroll 1
    for (int h = 0; h < 2; h++) {
        unsigned long long accB[24];
        #pragma unroll
        for (int u = 0; u < 24; u++) accB[u] = su[SA_BB / 2 + h * 24 + u];
        #pragma unroll 4
        for (int j = 0; j < 48; j++) {
            unsigned long long sp = splat2(a[j]);
            const ulonglong2* wr = su2 + SA_WB / 4 + (h * 48 + j) * 12;
            #pragma unroll
            for (int u2 = 0; u2 < 12; u2++) {
                ulonglong2 ww = wr[u2];
                fma2(accB[2 * u2], ww.x, sp);
                fma2(accB[2 * u2 + 1], ww.y, sp);
            }
        }
        #pragma unroll
        for (int u = 0; u < 24; u++) {
            float2 v = unpack2(accB[u]);
            unsigned long long s0 = splat2(fmaxf(v.x, 0.f));
            unsigned long long s1 = splat2(fmaxf(v.y, 0.f));
            int j0 = h * 48 + 2 * u;
            const ulonglong2* w0 = su2 + SA_WC / 4 + j0 * 3;
            ulonglong2 q0 = w0[0], q1 = w0[1], q2 = w0[2];
            fma2(oacc[0], q0.x, s0); fma2(oacc[1], q0.y, s0);
            fma2(oacc[2], q1.x, s0); fma2(oacc[3], q1.y, s0);
            fma2(oacc[4], q2.x, s0);
            ulonglong2 r0 = w0[3], r1 = w0[4], r2 = w0[5];
            fma2(oacc[0], r0.x, s1); fma2(oacc[1], r0.y, s1);
            fma2(oacc[2], r1.x, s1); fma2(oacc[3], r1.y, s1);
            fma2(oacc[4], r2.x, s1);
        }
    }

    float o9[9];
    #pragma unroll
    for (int pp = 0; pp < 4; pp++) {
        float2 v = unpack2(oacc[pp]);
        o9[2 * pp] = v.x; o9[2 * pp + 1] = v.y;
    }
    o9[8] = unpack2(oacc[4]).x;

    float xv = x[gp];
    float mx = fmaxf(o9[6], fmaxf(o9[7], o9[8]));
    float e0 = expf(o9[6] - mx), e1 = expf(o9[7] - mx), e2 = expf(o9[8] - mx);
    float inv = 1.f / (e0 + e1 + e2);
    float wsm[3] = {e0 * inv, e1 * inv, e2 * inv};

    float p3 = 0.f;
    #pragma unroll
    for (int k = 0; k < 3; k++) {
        float mu = o9[k];
        float scv = o9[3 + k];
        if (scv == 0.f) scv = 1e-9f;
        scv = fabsf(scv);
        float invs = 1.f / scv;
        float l = fabsf(normcdff((xv + 0.5f - mu) * invs)
                      - normcdff((xv - 0.5f - mu) * invs));
        p3 = fmaf(wsm[k], l, p3);
    }

    out[gp] = p3;
    #pragma unroll
    for (int o = 0; o < 9; o++)
        out[(size_t)VOX + (size_t)o * VOX + gp] = o9[o];
}

extern "C" void kernel_launch(void* const* d_in, const int* in_sizes, int n_in,
                              void* d_out, int out_size) {
    const float* x     = (const float*)d_in[0];
    const float* hyper = (const float*)d_in[1];
    const float* W3    = (const float*)d_in[2];
    const float* b3    = (const float*)d_in[3];
    const float* W1    = (const float*)d_in[4];
    const float* b1    = (const float*)d_in[5];
    const float* Wa    = (const float*)d_in[6];
    const float* ba    = (const float*)d_in[7];
    const float* Wb    = (const float*)d_in[8];
    const float* bb    = (const float*)d_in[9];
    const float* Wc    = (const float*)d_in[10];
    const float* bc    = (const float*)d_in[11];
    float* out = (float*)d_out;

    cudaFuncSetAttribute(conv3d_kernel,
                         cudaFuncAttributeMaxDynamicSharedMemorySize, K2_SMEM);

    pack_kernel<<<128, 256>>>(W3, W1, Wa, ba, Wb, bb, Wc, bc);
    conv2d_kernel<<<288, 192>>>(hyper, b3);
    conv3d_kernel<<<768, 576, K2_SMEM>>>(x, b1);
    mlp_kernel<<<VOX / 256, 256>>>(x, out);
}